// round 12
// baseline (speedup 1.0000x reference)
#include <cuda_runtime.h>
#include <cuda_fp16.h>
#include <math.h>

// Problem constants (DepthNet_20512763806141)
#define Bv 2
#define Vv 3
#define Cv 8
#define Hv 128
#define Wv 160
#define Dv 64
#define HWv (Hv * Wv)
#define TILES_PER_B (HWv / 32)

typedef unsigned long long u64;

// packed f32x2 helpers (SASS FFMA2/FADD2/FMUL2 — PTX-only on sm_103a)
__device__ __forceinline__ u64 pk2(float x, float y) {
    u64 r; asm("mov.b64 %0,{%1,%2};" : "=l"(r) : "f"(x), "f"(y)); return r;
}
__device__ __forceinline__ float2 upk2(u64 v) {
    float2 f; asm("mov.b64 {%0,%1},%2;" : "=f"(f.x), "=f"(f.y) : "l"(v)); return f;
}
__device__ __forceinline__ u64 fma2(u64 a, u64 b, u64 c) {
    u64 d; asm("fma.rn.f32x2 %0,%1,%2,%3;" : "=l"(d) : "l"(a), "l"(b), "l"(c)); return d;
}
__device__ __forceinline__ u64 mul2(u64 a, u64 b) {
    u64 d; asm("mul.rn.f32x2 %0,%1,%2;" : "=l"(d) : "l"(a), "l"(b)); return d;
}
__device__ __forceinline__ u64 add2(u64 a, u64 b) {
    u64 d; asm("add.rn.f32x2 %0,%1,%2;" : "=l"(d) : "l"(a), "l"(b)); return d;
}
__device__ __forceinline__ u64 h2tof2(__half2 h) {
    float2 f = __half22float2(h); return pk2(f.x, f.y);
}

// Features fp16 [V,B,HW,C] (16B per pixel record).
__device__ __half g_featH[Vv * Bv * HWv * Cv];

// ---------------------------------------------------------------------------
// Kernel 1: features [V,B,C,H,W] f32 -> [V,B,HW,C] fp16.
// ---------------------------------------------------------------------------
__global__ void feat_prep_kernel(const float* __restrict__ f) {
    const int idx = blockIdx.x * blockDim.x + threadIdx.x;  // over V*B*HW*2
    const int N = Vv * Bv * HWv * 2;
    if (idx >= N) return;
    const int half = idx & 1;
    const int pix  = (idx >> 1) % HWv;
    const int vb   = (idx >> 1) / HWv;
    const float* src = f + ((size_t)vb * Cv + half * 4) * HWv + pix;
    const float a = src[0];
    const float b = src[HWv];
    const float c = src[2 * HWv];
    const float d = src[3 * HWv];
    __half2 o[2];
    o[0] = __floats2half2_rn(a, b);
    o[1] = __floats2half2_rn(c, d);
    ((uint2*)g_featH)[idx] = *(const uint2*)o;
}

// ---------------------------------------------------------------------------
// Kernel 2: block = 4 warps = one tile of 32 consecutive pixels.
// lane = pixel, warp wid handles depths [16*wid, 16*wid+16), branchless
// online softmax; partials merged across warps via smem log-sum-exp.
// WARP-UNIFORM interior fast path: when all 32 lanes sample strictly inside
// the view (the common case), skip masks/clamps entirely — one VOTE + BRA,
// no divergence. Else path is the full masked/outside handling.
// ---------------------------------------------------------------------------
__global__ void __launch_bounds__(128, 9)
depthnet_kernel(const float* __restrict__ proj,      // [B,V,3,4]
                const float* __restrict__ depthv,    // [B,D,HW]
                const float* __restrict__ rw,        // [C]
                float* __restrict__ out)             // [B,HW]
{
    __shared__ float s_m[4][32], s_den[4][32], s_num[4][32];
    __shared__ float2 s_rw2[Cv / 2];

    const int lane = threadIdx.x & 31;
    const int wid  = threadIdx.x >> 5;
    const int tile = blockIdx.x;                 // 0 .. Bv*TILES_PER_B-1
    const int b    = tile / TILES_PER_B;
    const int hw   = (tile % TILES_PER_B) * 32 + lane;  // 32 | W, no row cross
    const int h    = hw / Wv;
    const int w    = hw % Wv;
    const float xf = (float)w, yf = (float)h;

    if (threadIdx.x < Cv / 2)
        s_rw2[threadIdx.x] = make_float2(rw[2 * threadIdx.x], rw[2 * threadIdx.x + 1]);

    // reference view features: 32 consecutive 16B records -> packed f32x2
    u64 ref2[4];
    {
        uint4 rv = ((const uint4*)g_featH)[(size_t)b * HWv + hw];
        const __half2* hp = (const __half2*)&rv;
#pragma unroll
        for (int j = 0; j < 4; j++) ref2[j] = h2tof2(hp[j]);
    }

    // per-source-view projection basis: rp = R @ [x,y,1], Tv = T column
    float rp[2][3], Tv[2][3];
#pragma unroll
    for (int i = 0; i < 2; i++) {
        const float* P = proj + (size_t)(b * Vv + (i + 1)) * 12;
#pragma unroll
        for (int r = 0; r < 3; r++) {
            float R0 = __ldg(&P[r * 4 + 0]);
            float R1 = __ldg(&P[r * 4 + 1]);
            float R2 = __ldg(&P[r * 4 + 2]);
            Tv[i][r] = __ldg(&P[r * 4 + 3]);
            rp[i][r] = fmaf(R0, xf, fmaf(R1, yf, R2));
        }
    }

    __syncthreads();   // s_rw2 ready

    // online softmax accumulators over this warp's 16 depths
    float m = -INFINITY, den = 0.0f, num = 0.0f;
    const int d0 = wid * 16;
    const float* depbase = depthv + (size_t)(b * Dv + d0) * HWv + hw;

#pragma unroll 4
    for (int t = 0; t < 16; t++) {
        const float dep = depbase[(size_t)t * HWv];   // coalesced

        u64 sum2[4], sq2[4];
#pragma unroll
        for (int j = 0; j < 4; j++) {
            sum2[j] = ref2[j];
            sq2[j]  = mul2(ref2[j], ref2[j]);
        }
        int nm = 1;

#pragma unroll
        for (int i = 0; i < 2; i++) {
            // ix = (rp0*d + T0)/(rp2*d + T2)
            const float nx = fmaf(rp[i][0], dep, Tv[i][0]);
            const float ny = fmaf(rp[i][1], dep, Tv[i][1]);
            const float nz = fmaf(rp[i][2], dep, Tv[i][2]);
            const float rz = __fdividef(1.0f, nz);
            const float ix = nx * rz;
            const float iy = ny * rz;

            const uint4* base = (const uint4*)g_featH +
                                (size_t)((i + 1) * Bv + b) * HWv;

            // strict interior (grid in (-1,1)); NaN compares false
            const bool interior = (ix > 0.0f) && (ix < (float)(Wv - 1)) &&
                                  (iy > 0.0f) && (iy < (float)(Hv - 1));
            nm += interior ? 1 : 0;

            u64 wv2[4];
            if (__all_sync(0xffffffffu, interior)) {
                // WARP-UNIFORM FAST PATH: no masks, no clamps.
                // x0 in [0,W-2], y0 in [0,H-2] guaranteed.
                const int x0 = __float2int_rd(ix);
                const int y0 = __float2int_rd(iy);
                const float fx = ix - (float)x0;
                const float fy = iy - (float)y0;
                const float gx1 = 1.0f - fx, gy1 = 1.0f - fy;

                const uint4* p = base + (y0 * Wv + x0);
                uint4 u00 = p[0];
                uint4 u10 = p[1];
                uint4 u01 = p[Wv];
                uint4 u11 = p[Wv + 1];

                const __half2 W00 = __float2half2_rn(gx1 * gy1);
                const __half2 W10 = __float2half2_rn(fx * gy1);
                const __half2 W01 = __float2half2_rn(gx1 * fy);
                const __half2 W11 = __float2half2_rn(fx * fy);

                const __half2* c00 = (const __half2*)&u00;
                const __half2* c10 = (const __half2*)&u10;
                const __half2* c01 = (const __half2*)&u01;
                const __half2* c11 = (const __half2*)&u11;
#pragma unroll
                for (int j = 0; j < 4; j++) {
                    __half2 acc = __hmul2(c00[j], W00);
                    acc = __hfma2(c10[j], W10, acc);
                    acc = __hfma2(c01[j], W01, acc);
                    acc = __hfma2(c11[j], W11, acc);
                    wv2[j] = h2tof2(acc);
                }
            } else {
                // GENERAL PATH (verbatim R6): masked weights, clamps, outside.
                const bool near = (ix > -1.0f) && (ix < (float)Wv) &&
                                  (iy > -1.0f) && (iy < (float)Hv);
                if (near) {
                    const int x0 = __float2int_rd(ix);
                    const int y0 = __float2int_rd(iy);
                    const float fx = ix - (float)x0;
                    const float fy = iy - (float)y0;
                    const float gx1 = 1.0f - fx, gy1 = 1.0f - fy;
                    float w00 = gx1 * gy1, w10 = fx * gy1, w01 = gx1 * fy, w11 = fx * fy;
                    if (x0 < 0)          { w00 = 0.0f; w01 = 0.0f; }
                    if (x0 + 1 > Wv - 1) { w10 = 0.0f; w11 = 0.0f; }
                    if (y0 < 0)          { w00 = 0.0f; w10 = 0.0f; }
                    if (y0 + 1 > Hv - 1) { w01 = 0.0f; w11 = 0.0f; }
                    const int xc0 = max(x0, 0);
                    const int yc0 = max(y0, 0);
                    const int dx  = (x0 >= 0 && x0 < Wv - 1) ? 1 : 0;
                    const int dy  = (y0 >= 0 && y0 < Hv - 1) ? Wv : 0;

                    const uint4* p00 = base + (yc0 * Wv + xc0);
                    uint4 u00 = p00[0];
                    uint4 u10 = p00[dx];
                    uint4 u01 = p00[dy];
                    uint4 u11 = p00[dy + dx];

                    const __half2 W00 = __float2half2_rn(w00);
                    const __half2 W10 = __float2half2_rn(w10);
                    const __half2 W01 = __float2half2_rn(w01);
                    const __half2 W11 = __float2half2_rn(w11);

                    const __half2* c00 = (const __half2*)&u00;
                    const __half2* c10 = (const __half2*)&u10;
                    const __half2* c01 = (const __half2*)&u01;
                    const __half2* c11 = (const __half2*)&u11;
#pragma unroll
                    for (int j = 0; j < 4; j++) {
                        __half2 acc = __hmul2(c00[j], W00);
                        acc = __hfma2(c10[j], W10, acc);
                        acc = __hfma2(c01[j], W01, acc);
                        acc = __hfma2(c11[j], W11, acc);
                        wv2[j] = h2tof2(acc);
                    }
                } else {
                    // fully outside: 0 if coords finite, NaN if not
                    const float nv = (isfinite(ix) && isfinite(iy))
                                         ? 0.0f
                                         : __int_as_float(0x7fffffff);
                    const u64 nv2 = pk2(nv, nv);
#pragma unroll
                    for (int j = 0; j < 4; j++) wv2[j] = nv2;
                }
            }

#pragma unroll
            for (int j = 0; j < 4; j++) {
                sum2[j] = add2(sum2[j], wv2[j]);
                sq2[j]  = fma2(wv2[j], wv2[j], sq2[j]);
            }
        }

        // cnt = 1/nm without MUFU (nm in {1,2,3})
        const float cnt = (nm == 1) ? 1.0f : ((nm == 2) ? 0.5f : (1.0f / 3.0f));
        const u64 cnt2  = pk2(cnt, cnt);
        const u64 ncnt2 = pk2(-cnt, -cnt);

        u64 acc2 = pk2(0.0f, 0.0f);
#pragma unroll
        for (int j = 0; j < 4; j++) {
            const float2 rwj = s_rw2[j];
            const u64 rw2j = pk2(rwj.x, rwj.y);
            const u64 mean2 = mul2(sum2[j], cnt2);
            const u64 mneg2 = mul2(sum2[j], ncnt2);
            const u64 feat2 = fma2(mneg2, mean2, mul2(sq2[j], cnt2));
            acc2 = fma2(feat2, rw2j, acc2);
        }
        const float2 ac = upk2(acc2);
        const float cst = ac.x + ac.y;

        // branchless online softmax update
        const float newm = fmaxf(m, cst);
        const float e_old = __expf(m - newm);
        const float e_new = __expf(cst - newm);
        den = fmaf(den, e_old, e_new);
        num = fmaf(num, e_old, e_new * dep);
        m = newm;
    }

    s_m[wid][lane]   = m;
    s_den[wid][lane] = den;
    s_num[wid][lane] = num;
    __syncthreads();

    // warp 0 merges the 4 partial softmaxes per pixel (log-sum-exp)
    if (wid == 0) {
        float M = s_m[0][lane];
#pragma unroll
        for (int j = 1; j < 4; j++) M = fmaxf(M, s_m[j][lane]);
        float D = 0.0f, N = 0.0f;
#pragma unroll
        for (int j = 0; j < 4; j++) {
            const float e = __expf(s_m[j][lane] - M);
            D = fmaf(s_den[j][lane], e, D);
            N = fmaf(s_num[j][lane], e, N);
        }
        out[(size_t)b * HWv + (tile % TILES_PER_B) * 32 + lane] = __fdividef(N, D);
    }
}

// ---------------------------------------------------------------------------
extern "C" void kernel_launch(void* const* d_in, const int* in_sizes, int n_in,
                              void* d_out, int out_size) {
    const float* features = (const float*)d_in[0];  // [V,B,C,H,W]
    const float* proj     = (const float*)d_in[1];  // [B,V,3,4]
    const float* depthv   = (const float*)d_in[2];  // [B,D,H,W]
    const float* rw       = (const float*)d_in[3];  // [C]
    float* out            = (float*)d_out;          // [B,HW]
    (void)in_sizes; (void)n_in; (void)out_size;

    // 1) features -> fp16 [V,B,HW,C]
    const int nP = Vv * Bv * HWv * 2;
    feat_prep_kernel<<<(nP + 255) / 256, 256>>>(features);

    // 2) main fused kernel: 32-pixel tile per block, 4 depth-chunk warps,
    //    one wave (9 blocks/SM).
    const int ntiles = Bv * TILES_PER_B;   // 1280
    depthnet_kernel<<<ntiles, 128>>>(proj, depthv, rw, out);
}

// round 13
// speedup vs baseline: 1.4642x; 1.4642x over previous
#include <cuda_runtime.h>
#include <cuda_fp16.h>
#include <math.h>

// Problem constants (DepthNet_20512763806141)
#define Bv 2
#define Vv 3
#define Cv 8
#define Hv 128
#define Wv 160
#define Dv 64
#define HWv (Hv * Wv)
#define TILES_PER_B (HWv / 32)

typedef unsigned long long u64;

// packed f32x2 helpers (SASS FFMA2/FADD2/FMUL2 — PTX-only on sm_103a)
__device__ __forceinline__ u64 pk2(float x, float y) {
    u64 r; asm("mov.b64 %0,{%1,%2};" : "=l"(r) : "f"(x), "f"(y)); return r;
}
__device__ __forceinline__ float2 upk2(u64 v) {
    float2 f; asm("mov.b64 {%0,%1},%2;" : "=f"(f.x), "=f"(f.y) : "l"(v)); return f;
}
__device__ __forceinline__ u64 fma2(u64 a, u64 b, u64 c) {
    u64 d; asm("fma.rn.f32x2 %0,%1,%2,%3;" : "=l"(d) : "l"(a), "l"(b), "l"(c)); return d;
}
__device__ __forceinline__ u64 mul2(u64 a, u64 b) {
    u64 d; asm("mul.rn.f32x2 %0,%1,%2;" : "=l"(d) : "l"(a), "l"(b)); return d;
}
__device__ __forceinline__ u64 add2(u64 a, u64 b) {
    u64 d; asm("add.rn.f32x2 %0,%1,%2;" : "=l"(d) : "l"(a), "l"(b)); return d;
}
__device__ __forceinline__ u64 h2tof2(__half2 h) {
    float2 f = __half22float2(h); return pk2(f.x, f.y);
}

// Features fp16 [V,B,HW,C] (16B per pixel record).
__device__ __half g_featH[Vv * Bv * HWv * Cv];

// ---------------------------------------------------------------------------
// Kernel 1: features [V,B,C,H,W] f32 -> [V,B,HW,C] fp16.
// ---------------------------------------------------------------------------
__global__ void feat_prep_kernel(const float* __restrict__ f) {
    const int idx = blockIdx.x * blockDim.x + threadIdx.x;  // over V*B*HW*2
    const int N = Vv * Bv * HWv * 2;
    if (idx >= N) return;
    const int half = idx & 1;
    const int pix  = (idx >> 1) % HWv;
    const int vb   = (idx >> 1) / HWv;
    const float* src = f + ((size_t)vb * Cv + half * 4) * HWv + pix;
    const float a = src[0];
    const float b = src[HWv];
    const float c = src[2 * HWv];
    const float d = src[3 * HWv];
    __half2 o[2];
    o[0] = __floats2half2_rn(a, b);
    o[1] = __floats2half2_rn(c, d);
    ((uint2*)g_featH)[idx] = *(const uint2*)o;
}

// ---------------------------------------------------------------------------
// Kernel 2: block = 4 warps = one tile of 32 consecutive pixels.
// lane = pixel, warp wid handles depths [16*wid, 16*wid+16), branchless
// online softmax; partials merged across warps via smem log-sum-exp.
// (R6 structure — the empirically best shape — with a regrouped, smaller
// cost epilogue: cost = cnt*Asq - cnt^2*Asum, rw kept OUT of the blend loop.)
// ---------------------------------------------------------------------------
__global__ void __launch_bounds__(128, 9)
depthnet_kernel(const float* __restrict__ proj,      // [B,V,3,4]
                const float* __restrict__ depthv,    // [B,D,HW]
                const float* __restrict__ rw,        // [C]
                float* __restrict__ out)             // [B,HW]
{
    __shared__ float s_m[4][32], s_den[4][32], s_num[4][32];
    __shared__ u64 s_rw2[Cv / 2];

    const int lane = threadIdx.x & 31;
    const int wid  = threadIdx.x >> 5;
    const int tile = blockIdx.x;                 // 0 .. Bv*TILES_PER_B-1
    const int b    = tile / TILES_PER_B;
    const int hw   = (tile % TILES_PER_B) * 32 + lane;  // 32 | W, no row cross
    const int h    = hw / Wv;
    const int w    = hw % Wv;
    const float xf = (float)w, yf = (float)h;

    if (threadIdx.x < Cv / 2)
        s_rw2[threadIdx.x] = pk2(rw[2 * threadIdx.x], rw[2 * threadIdx.x + 1]);

    // reference view features: 32 consecutive 16B records -> packed f32x2
    u64 ref2[4];
    {
        uint4 rv = ((const uint4*)g_featH)[(size_t)b * HWv + hw];
        const __half2* hp = (const __half2*)&rv;
#pragma unroll
        for (int j = 0; j < 4; j++) ref2[j] = h2tof2(hp[j]);
    }

    // per-source-view projection basis: rp = R @ [x,y,1], Tv = T column
    float rp[2][3], Tv[2][3];
#pragma unroll
    for (int i = 0; i < 2; i++) {
        const float* P = proj + (size_t)(b * Vv + (i + 1)) * 12;
#pragma unroll
        for (int r = 0; r < 3; r++) {
            float R0 = __ldg(&P[r * 4 + 0]);
            float R1 = __ldg(&P[r * 4 + 1]);
            float R2 = __ldg(&P[r * 4 + 2]);
            Tv[i][r] = __ldg(&P[r * 4 + 3]);
            rp[i][r] = fmaf(R0, xf, fmaf(R1, yf, R2));
        }
    }

    __syncthreads();   // s_rw2 ready

    // online softmax accumulators over this warp's 16 depths
    float m = -INFINITY, den = 0.0f, num = 0.0f;
    const int d0 = wid * 16;
    const float* depbase = depthv + (size_t)(b * Dv + d0) * HWv + hw;

#pragma unroll 4
    for (int t = 0; t < 16; t++) {
        const float dep = depbase[(size_t)t * HWv];   // coalesced

        u64 sum2[4], sq2[4];
#pragma unroll
        for (int j = 0; j < 4; j++) {
            sum2[j] = ref2[j];
            sq2[j]  = mul2(ref2[j], ref2[j]);
        }
        int nm = 1;

#pragma unroll
        for (int i = 0; i < 2; i++) {
            // ix = (rp0*d + T0)/(rp2*d + T2)
            const float nx = fmaf(rp[i][0], dep, Tv[i][0]);
            const float ny = fmaf(rp[i][1], dep, Tv[i][1]);
            const float nz = fmaf(rp[i][2], dep, Tv[i][2]);
            const float rz = __fdividef(1.0f, nz);
            const float ix = nx * rz;
            const float iy = ny * rz;

            // strict interior (grid in (-1,1)); NaN compares false
            if (ix > 0.0f && ix < (float)(Wv - 1) && iy > 0.0f && iy < (float)(Hv - 1))
                nm++;

            u64 wv2[4];
            const bool near = (ix > -1.0f) && (ix < (float)Wv) &&
                              (iy > -1.0f) && (iy < (float)Hv);
            if (near) {
                const int x0 = __float2int_rd(ix);
                const int y0 = __float2int_rd(iy);
                const float fx = ix - (float)x0;
                const float fy = iy - (float)y0;
                const float gx1 = 1.0f - fx, gy1 = 1.0f - fy;
                float w00 = gx1 * gy1, w10 = fx * gy1, w01 = gx1 * fy, w11 = fx * fy;
                if (x0 < 0)          { w00 = 0.0f; w01 = 0.0f; }
                if (x0 + 1 > Wv - 1) { w10 = 0.0f; w11 = 0.0f; }
                if (y0 < 0)          { w00 = 0.0f; w10 = 0.0f; }
                if (y0 + 1 > Hv - 1) { w01 = 0.0f; w11 = 0.0f; }
                // incremental corner addressing: dx in {0,1}, dy in {0,W}
                const int xc0 = max(x0, 0);
                const int yc0 = max(y0, 0);
                const int dx  = (x0 >= 0 && x0 < Wv - 1) ? 1 : 0;
                const int dy  = (y0 >= 0 && y0 < Hv - 1) ? Wv : 0;

                const uint4* p00 = (const uint4*)g_featH +
                                   (size_t)((i + 1) * Bv + b) * HWv +
                                   (yc0 * Wv + xc0);
                uint4 u00 = p00[0];
                uint4 u10 = p00[dx];
                uint4 u01 = p00[dy];
                uint4 u11 = p00[dy + dx];

                const __half2 W00 = __float2half2_rn(w00);
                const __half2 W10 = __float2half2_rn(w10);
                const __half2 W01 = __float2half2_rn(w01);
                const __half2 W11 = __float2half2_rn(w11);

                const __half2* c00 = (const __half2*)&u00;
                const __half2* c10 = (const __half2*)&u10;
                const __half2* c01 = (const __half2*)&u01;
                const __half2* c11 = (const __half2*)&u11;
#pragma unroll
                for (int j = 0; j < 4; j++) {
                    __half2 acc = __hmul2(c00[j], W00);
                    acc = __hfma2(c10[j], W10, acc);
                    acc = __hfma2(c01[j], W01, acc);
                    acc = __hfma2(c11[j], W11, acc);
                    wv2[j] = h2tof2(acc);
                }
            } else {
                // fully outside: 0 if coords finite, NaN if not
                const float nv = (isfinite(ix) && isfinite(iy))
                                     ? 0.0f
                                     : __int_as_float(0x7fffffff);
                const u64 nv2 = pk2(nv, nv);
#pragma unroll
                for (int j = 0; j < 4; j++) wv2[j] = nv2;
            }

#pragma unroll
            for (int j = 0; j < 4; j++) {
                sum2[j] = add2(sum2[j], wv2[j]);
                sq2[j]  = fma2(wv2[j], wv2[j], sq2[j]);
            }
        }

        // cnt = 1/nm without MUFU (nm in {1,2,3})
        const float cnt = (nm == 1) ? 1.0f : ((nm == 2) ? 0.5f : (1.0f / 3.0f));

        // regrouped epilogue: Asq = sum_c rw*sq, Asum = sum_c rw*sum^2
        u64 Asq2  = pk2(0.0f, 0.0f);
        u64 Asum2 = pk2(0.0f, 0.0f);
#pragma unroll
        for (int j = 0; j < 4; j++) {
            const u64 rw2j = s_rw2[j];
            Asq2  = fma2(sq2[j], rw2j, Asq2);
            Asum2 = fma2(mul2(sum2[j], sum2[j]), rw2j, Asum2);
        }
        const float2 aq = upk2(Asq2);
        const float2 as = upk2(Asum2);
        const float Asq  = aq.x + aq.y;
        const float Asum = as.x + as.y;
        // cost = cnt*Asq - cnt^2*Asum
        const float cst = fmaf(-cnt * cnt, Asum, cnt * Asq);

        // branchless online softmax update
        const float newm = fmaxf(m, cst);
        const float e_old = __expf(m - newm);
        const float e_new = __expf(cst - newm);
        den = fmaf(den, e_old, e_new);
        num = fmaf(num, e_old, e_new * dep);
        m = newm;
    }

    s_m[wid][lane]   = m;
    s_den[wid][lane] = den;
    s_num[wid][lane] = num;
    __syncthreads();

    // warp 0 merges the 4 partial softmaxes per pixel (log-sum-exp)
    if (wid == 0) {
        float M = s_m[0][lane];
#pragma unroll
        for (int j = 1; j < 4; j++) M = fmaxf(M, s_m[j][lane]);
        float D = 0.0f, N = 0.0f;
#pragma unroll
        for (int j = 0; j < 4; j++) {
            const float e = __expf(s_m[j][lane] - M);
            D = fmaf(s_den[j][lane], e, D);
            N = fmaf(s_num[j][lane], e, N);
        }
        out[(size_t)b * HWv + (tile % TILES_PER_B) * 32 + lane] = __fdividef(N, D);
    }
}

// ---------------------------------------------------------------------------
extern "C" void kernel_launch(void* const* d_in, const int* in_sizes, int n_in,
                              void* d_out, int out_size) {
    const float* features = (const float*)d_in[0];  // [V,B,C,H,W]
    const float* proj     = (const float*)d_in[1];  // [B,V,3,4]
    const float* depthv   = (const float*)d_in[2];  // [B,D,H,W]
    const float* rw       = (const float*)d_in[3];  // [C]
    float* out            = (float*)d_out;          // [B,HW]
    (void)in_sizes; (void)n_in; (void)out_size;

    // 1) features -> fp16 [V,B,HW,C]
    const int nP = Vv * Bv * HWv * 2;
    feat_prep_kernel<<<(nP + 255) / 256, 256>>>(features);

    // 2) main fused kernel: 32-pixel tile per block, 4 depth-chunk warps,
    //    one wave (9 blocks/SM).
    const int ntiles = Bv * TILES_PER_B;   // 1280
    depthnet_kernel<<<ntiles, 128>>>(proj, depthv, rw, out);
}

// round 15
// speedup vs baseline: 1.5514x; 1.0596x over previous
#include <cuda_runtime.h>
#include <cuda_fp16.h>
#include <math.h>

// Problem constants (DepthNet_20512763806141)
#define Bv 2
#define Vv 3
#define Cv 8
#define Hv 128
#define Wv 160
#define Dv 64
#define HWv (Hv * Wv)
#define TILES_PER_B (HWv / 32)

typedef unsigned long long u64;

// packed f32x2 helpers (SASS FFMA2/FADD2/FMUL2 — PTX-only on sm_103a)
__device__ __forceinline__ u64 pk2(float x, float y) {
    u64 r; asm("mov.b64 %0,{%1,%2};" : "=l"(r) : "f"(x), "f"(y)); return r;
}
__device__ __forceinline__ float2 upk2(u64 v) {
    float2 f; asm("mov.b64 {%0,%1},%2;" : "=f"(f.x), "=f"(f.y) : "l"(v)); return f;
}
__device__ __forceinline__ u64 fma2(u64 a, u64 b, u64 c) {
    u64 d; asm("fma.rn.f32x2 %0,%1,%2,%3;" : "=l"(d) : "l"(a), "l"(b), "l"(c)); return d;
}
__device__ __forceinline__ u64 mul2(u64 a, u64 b) {
    u64 d; asm("mul.rn.f32x2 %0,%1,%2;" : "=l"(d) : "l"(a), "l"(b)); return d;
}
__device__ __forceinline__ u64 add2(u64 a, u64 b) {
    u64 d; asm("add.rn.f32x2 %0,%1,%2;" : "=l"(d) : "l"(a), "l"(b)); return d;
}
__device__ __forceinline__ u64 h2tof2(__half2 h) {
    float2 f = __half22float2(h); return pk2(f.x, f.y);
}

// Features fp16 [V,B,HW,C] (16B per pixel record).
__device__ __half g_featH[Vv * Bv * HWv * Cv];

// ---------------------------------------------------------------------------
// Kernel 1: features [V,B,C,H,W] f32 -> [V,B,HW,C] fp16.
// One thread per (pixel, channel-PAIR): 2 fp32 loads, one coalesced 4B store.
// 245,760 threads / 960 blocks — 2x the parallelism of the pixel-half version
// (this kernel is pure latency-bound; more warps = more MLP).
// ---------------------------------------------------------------------------
__global__ void feat_prep_kernel(const float* __restrict__ f) {
    const int idx = blockIdx.x * blockDim.x + threadIdx.x;  // over V*B*HW*4
    const int N = Vv * Bv * HWv * 4;
    if (idx >= N) return;
    const int q   = idx & 3;            // channel pair 0..3
    const int pix = (idx >> 2) % HWv;
    const int vb  = (idx >> 2) / HWv;
    const float* src = f + ((size_t)vb * Cv + 2 * q) * HWv + pix;
    const float a = src[0];
    const float b = src[HWv];
    ((__half2*)g_featH)[idx] = __floats2half2_rn(a, b);
}

// ---------------------------------------------------------------------------
// Kernel 2 (R6 verbatim — empirically best): block = 4 warps = one tile of
// 32 consecutive pixels. lane = pixel, warp wid handles depths
// [16*wid, 16*wid+16), branchless online softmax; partials merged across
// warps via smem log-sum-exp.
// ---------------------------------------------------------------------------
__global__ void __launch_bounds__(128, 9)
depthnet_kernel(const float* __restrict__ proj,      // [B,V,3,4]
                const float* __restrict__ depthv,    // [B,D,HW]
                const float* __restrict__ rw,        // [C]
                float* __restrict__ out)             // [B,HW]
{
    __shared__ float s_m[4][32], s_den[4][32], s_num[4][32];
    __shared__ float2 s_rw2[Cv / 2];

    const int lane = threadIdx.x & 31;
    const int wid  = threadIdx.x >> 5;
    const int tile = blockIdx.x;                 // 0 .. Bv*TILES_PER_B-1
    const int b    = tile / TILES_PER_B;
    const int hw   = (tile % TILES_PER_B) * 32 + lane;  // 32 | W, no row cross
    const int h    = hw / Wv;
    const int w    = hw % Wv;
    const float xf = (float)w, yf = (float)h;

    if (threadIdx.x < Cv / 2)
        s_rw2[threadIdx.x] = make_float2(rw[2 * threadIdx.x], rw[2 * threadIdx.x + 1]);

    // reference view features: 32 consecutive 16B records -> packed f32x2
    u64 ref2[4];
    {
        uint4 rv = ((const uint4*)g_featH)[(size_t)b * HWv + hw];
        const __half2* hp = (const __half2*)&rv;
#pragma unroll
        for (int j = 0; j < 4; j++) ref2[j] = h2tof2(hp[j]);
    }

    // per-source-view projection basis: rp = R @ [x,y,1], Tv = T column
    float rp[2][3], Tv[2][3];
#pragma unroll
    for (int i = 0; i < 2; i++) {
        const float* P = proj + (size_t)(b * Vv + (i + 1)) * 12;
#pragma unroll
        for (int r = 0; r < 3; r++) {
            float R0 = __ldg(&P[r * 4 + 0]);
            float R1 = __ldg(&P[r * 4 + 1]);
            float R2 = __ldg(&P[r * 4 + 2]);
            Tv[i][r] = __ldg(&P[r * 4 + 3]);
            rp[i][r] = fmaf(R0, xf, fmaf(R1, yf, R2));
        }
    }

    __syncthreads();   // s_rw2 ready

    // online softmax accumulators over this warp's 16 depths
    float m = -INFINITY, den = 0.0f, num = 0.0f;
    const int d0 = wid * 16;
    const float* depbase = depthv + (size_t)(b * Dv + d0) * HWv + hw;

#pragma unroll 4
    for (int t = 0; t < 16; t++) {
        const float dep = depbase[(size_t)t * HWv];   // coalesced

        u64 sum2[4], sq2[4];
#pragma unroll
        for (int j = 0; j < 4; j++) {
            sum2[j] = ref2[j];
            sq2[j]  = mul2(ref2[j], ref2[j]);
        }
        int nm = 1;

#pragma unroll
        for (int i = 0; i < 2; i++) {
            // ix = (rp0*d + T0)/(rp2*d + T2)
            const float nx = fmaf(rp[i][0], dep, Tv[i][0]);
            const float ny = fmaf(rp[i][1], dep, Tv[i][1]);
            const float nz = fmaf(rp[i][2], dep, Tv[i][2]);
            const float rz = __fdividef(1.0f, nz);
            const float ix = nx * rz;
            const float iy = ny * rz;

            // strict interior (grid in (-1,1)); NaN compares false
            if (ix > 0.0f && ix < (float)(Wv - 1) && iy > 0.0f && iy < (float)(Hv - 1))
                nm++;

            u64 wv2[4];
            const bool near = (ix > -1.0f) && (ix < (float)Wv) &&
                              (iy > -1.0f) && (iy < (float)Hv);
            if (near) {
                const int x0 = __float2int_rd(ix);
                const int y0 = __float2int_rd(iy);
                const float fx = ix - (float)x0;
                const float fy = iy - (float)y0;
                const float gx1 = 1.0f - fx, gy1 = 1.0f - fy;
                float w00 = gx1 * gy1, w10 = fx * gy1, w01 = gx1 * fy, w11 = fx * fy;
                if (x0 < 0)          { w00 = 0.0f; w01 = 0.0f; }
                if (x0 + 1 > Wv - 1) { w10 = 0.0f; w11 = 0.0f; }
                if (y0 < 0)          { w00 = 0.0f; w10 = 0.0f; }
                if (y0 + 1 > Hv - 1) { w01 = 0.0f; w11 = 0.0f; }
                // incremental corner addressing: dx in {0,1}, dy in {0,W}
                const int xc0 = max(x0, 0);
                const int yc0 = max(y0, 0);
                const int dx  = (x0 >= 0 && x0 < Wv - 1) ? 1 : 0;
                const int dy  = (y0 >= 0 && y0 < Hv - 1) ? Wv : 0;

                const uint4* p00 = (const uint4*)g_featH +
                                   (size_t)((i + 1) * Bv + b) * HWv +
                                   (yc0 * Wv + xc0);
                uint4 u00 = p00[0];
                uint4 u10 = p00[dx];
                uint4 u01 = p00[dy];
                uint4 u11 = p00[dy + dx];

                const __half2 W00 = __float2half2_rn(w00);
                const __half2 W10 = __float2half2_rn(w10);
                const __half2 W01 = __float2half2_rn(w01);
                const __half2 W11 = __float2half2_rn(w11);

                const __half2* c00 = (const __half2*)&u00;
                const __half2* c10 = (const __half2*)&u10;
                const __half2* c01 = (const __half2*)&u01;
                const __half2* c11 = (const __half2*)&u11;
#pragma unroll
                for (int j = 0; j < 4; j++) {
                    __half2 acc = __hmul2(c00[j], W00);
                    acc = __hfma2(c10[j], W10, acc);
                    acc = __hfma2(c01[j], W01, acc);
                    acc = __hfma2(c11[j], W11, acc);
                    wv2[j] = h2tof2(acc);
                }
            } else {
                // fully outside: 0 if coords finite, NaN if not
                const float nv = (isfinite(ix) && isfinite(iy))
                                     ? 0.0f
                                     : __int_as_float(0x7fffffff);
                const u64 nv2 = pk2(nv, nv);
#pragma unroll
                for (int j = 0; j < 4; j++) wv2[j] = nv2;
            }

#pragma unroll
            for (int j = 0; j < 4; j++) {
                sum2[j] = add2(sum2[j], wv2[j]);
                sq2[j]  = fma2(wv2[j], wv2[j], sq2[j]);
            }
        }

        // cnt = 1/nm without MUFU (nm in {1,2,3})
        const float cnt = (nm == 1) ? 1.0f : ((nm == 2) ? 0.5f : (1.0f / 3.0f));
        const u64 cnt2  = pk2(cnt, cnt);
        const u64 ncnt2 = pk2(-cnt, -cnt);

        u64 acc2 = pk2(0.0f, 0.0f);
#pragma unroll
        for (int j = 0; j < 4; j++) {
            const float2 rwj = s_rw2[j];
            const u64 rw2j = pk2(rwj.x, rwj.y);
            const u64 mean2 = mul2(sum2[j], cnt2);
            const u64 mneg2 = mul2(sum2[j], ncnt2);
            const u64 feat2 = fma2(mneg2, mean2, mul2(sq2[j], cnt2));
            acc2 = fma2(feat2, rw2j, acc2);
        }
        const float2 ac = upk2(acc2);
        const float cst = ac.x + ac.y;

        // branchless online softmax update
        const float newm = fmaxf(m, cst);
        const float e_old = __expf(m - newm);
        const float e_new = __expf(cst - newm);
        den = fmaf(den, e_old, e_new);
        num = fmaf(num, e_old, e_new * dep);
        m = newm;
    }

    s_m[wid][lane]   = m;
    s_den[wid][lane] = den;
    s_num[wid][lane] = num;
    __syncthreads();

    // warp 0 merges the 4 partial softmaxes per pixel (log-sum-exp)
    if (wid == 0) {
        float M = s_m[0][lane];
#pragma unroll
        for (int j = 1; j < 4; j++) M = fmaxf(M, s_m[j][lane]);
        float D = 0.0f, N = 0.0f;
#pragma unroll
        for (int j = 0; j < 4; j++) {
            const float e = __expf(s_m[j][lane] - M);
            D = fmaf(s_den[j][lane], e, D);
            N = fmaf(s_num[j][lane], e, N);
        }
        out[(size_t)b * HWv + (tile % TILES_PER_B) * 32 + lane] = __fdividef(N, D);
    }
}

// ---------------------------------------------------------------------------
extern "C" void kernel_launch(void* const* d_in, const int* in_sizes, int n_in,
                              void* d_out, int out_size) {
    const float* features = (const float*)d_in[0];  // [V,B,C,H,W]
    const float* proj     = (const float*)d_in[1];  // [B,V,3,4]
    const float* depthv   = (const float*)d_in[2];  // [B,D,H,W]
    const float* rw       = (const float*)d_in[3];  // [C]
    float* out            = (float*)d_out;          // [B,HW]
    (void)in_sizes; (void)n_in; (void)out_size;

    // 1) features -> fp16 [V,B,HW,C] (thread per channel-pair)
    const int nP = Vv * Bv * HWv * 4;
    feat_prep_kernel<<<(nP + 255) / 256, 256>>>(features);

    // 2) main fused kernel: 32-pixel tile per block, 4 depth-chunk warps,
    //    one wave (9 blocks/SM).
    const int ntiles = Bv * TILES_PER_B;   // 1280
    depthnet_kernel<<<ntiles, 128>>>(proj, depthv, rw, out);
}